// round 7
// baseline (speedup 1.0000x reference)
#include <cuda_runtime.h>
#include <cuda_bf16.h>
#include <cstdint>
#include <math.h>

#define SEQ 4096
#define H 2048
#define IN_DIM 2048
#define G3 6144

// ---------------- scratch ---------------------------------------------------
__device__ float g_igates[(size_t)SEQ * G3];   // ~100.7 MB
__device__ unsigned g_flags[128 * 32];         // zero-init; one 128B slot per CTA

// ---------------- Kernel 1: igates = xs @ Wi^T + bi (round-2 proven) -------
#define GBM 128
#define GBN 128
#define GBK 16

__global__ __launch_bounds__(256) void igates_gemm(
    const float* __restrict__ A,
    const float* __restrict__ B,
    const float* __restrict__ bias)
{
    __shared__ float As[GBK][GBM + 1];
    __shared__ float Bs[GBK][GBN + 1];

    const int bm = blockIdx.y * GBM;
    const int bn = blockIdx.x * GBN;
    const int tid = threadIdx.x;
    const int tx = tid & 15;
    const int ty = tid >> 4;
    const int lr = tid >> 2;
    const int lc = tid & 3;

    float acc[8][8];
    #pragma unroll
    for (int i = 0; i < 8; i++)
        #pragma unroll
        for (int j = 0; j < 8; j++) acc[i][j] = 0.f;

    for (int k0 = 0; k0 < IN_DIM; k0 += GBK) {
        #pragma unroll
        for (int s = 0; s < 2; s++) {
            const int row = lr + 64 * s;
            float4 va = *(const float4*)(A + (size_t)(bm + row) * IN_DIM + k0 + 4 * lc);
            As[4*lc+0][row] = va.x; As[4*lc+1][row] = va.y;
            As[4*lc+2][row] = va.z; As[4*lc+3][row] = va.w;
            float4 vb = *(const float4*)(B + (size_t)(bn + row) * IN_DIM + k0 + 4 * lc);
            Bs[4*lc+0][row] = vb.x; Bs[4*lc+1][row] = vb.y;
            Bs[4*lc+2][row] = vb.z; Bs[4*lc+3][row] = vb.w;
        }
        __syncthreads();

        #pragma unroll
        for (int k = 0; k < GBK; k++) {
            float a[8], b[8];
            #pragma unroll
            for (int i = 0; i < 8; i++) a[i] = As[k][ty * 8 + i];
            #pragma unroll
            for (int j = 0; j < 8; j++) b[j] = Bs[k][tx * 8 + j];
            #pragma unroll
            for (int i = 0; i < 8; i++)
                #pragma unroll
                for (int j = 0; j < 8; j++) acc[i][j] += a[i] * b[j];
        }
        __syncthreads();
    }

    #pragma unroll
    for (int i = 0; i < 8; i++) {
        const int row = bm + ty * 8 + i;
        const int col = bn + tx * 8;
        float4 o0, o1;
        o0.x = acc[i][0] + bias[col + 0];
        o0.y = acc[i][1] + bias[col + 1];
        o0.z = acc[i][2] + bias[col + 2];
        o0.w = acc[i][3] + bias[col + 3];
        o1.x = acc[i][4] + bias[col + 4];
        o1.y = acc[i][5] + bias[col + 5];
        o1.z = acc[i][6] + bias[col + 6];
        o1.w = acc[i][7] + bias[col + 7];
        float* cp = g_igates + (size_t)row * G3 + col;
        *(float4*)(cp + 0) = o0;
        *(float4*)(cp + 4) = o1;
    }
}

// ---------------- Kernel 2: persistent GRU recurrence ----------------------
#define NCTA 128
#define PER 16
#define NROWS 48
#define RTH 256

__device__ __forceinline__ float bf_lo(unsigned w) {
    return __uint_as_float(w << 16);
}
__device__ __forceinline__ float bf_hi(unsigned w) {
    return __uint_as_float(w & 0xFFFF0000u);
}
__device__ __forceinline__ unsigned ldflag(const unsigned* p) {
    unsigned v;
    asm volatile("ld.global.cg.u32 %0, [%1];" : "=r"(v) : "l"(p));
    return v;
}
__device__ __forceinline__ void stflag(unsigned* p, unsigned v) {
    asm volatile("st.global.cg.u32 [%0], %1;" :: "l"(p), "r"(v) : "memory");
}
__device__ __forceinline__ float fsig(float x) {
    return __fdividef(1.f, 1.f + __expf(-x));
}
__device__ __forceinline__ float ftanh(float x) {
    return __fdividef(2.f, 1.f + __expf(-2.f * x)) - 1.f;
}

__global__ __launch_bounds__(RTH, 1) void gru_recur(
    const float* __restrict__ init_state,
    const float* __restrict__ Wh,
    const float* __restrict__ bn,
    float* __restrict__ out)
{
    extern __shared__ float smem[];
    unsigned* wc = (unsigned*)smem;                       // NROWS * H/2 words
    float* red   = (float*)(wc + (size_t)NROWS * (H/2));  // NROWS floats
    __shared__ unsigned base_sh;

    const int tid  = threadIdx.x;
    const int lane = tid & 31;
    const int wid  = tid >> 5;
    const int bid  = blockIdx.x;
    const int base = bid * PER;
    const int r0   = wid * 6;            // this warp's 6 rows

    // prologue: convert+cache 48 Wh rows as packed bf16 (lo=elem 2v, hi=2v+1)
    for (int r = 0; r < NROWS; r++) {
        const int gate = r / PER, i = r % PER;
        const float2* src = (const float2*)(Wh + (size_t)(gate * H + base + i) * H);
        unsigned* dst = wc + (size_t)r * (H / 2);
        for (int v = tid; v < H / 2; v += RTH) {
            float2 w = src[v];
            __nv_bfloat162 b2 = __floats2bfloat162_rn(w.x, w.y);
            dst[v] = *(unsigned*)&b2;
        }
    }
    if (tid == 0) base_sh = ldflag(&g_flags[bid * 32]);   // epoch base (monotonic)
    __syncthreads();   // orders wc writes + base_sh vs first reads
    const unsigned fbase = base_sh;

    float bnv = 0.f, lastv = 0.f;
    if (tid < PER) bnv = bn[base + tid];

    for (int t = 0; t < SEQ; t++) {
        const float* hprev = (t == 0) ? init_state : (out + (size_t)(t - 1) * H);

        // early reads: igates (DRAM) + own h_{t-1}; consumed in the epilogue
        float gr = 0.f, gz = 0.f, gn = 0.f, hmine = 0.f;
        if (tid < PER) {
            const float* ig = g_igates + (size_t)t * G3;
            gr = ig[base + tid];
            gz = ig[H + base + tid];
            gn = ig[2 * H + base + tid];
            hmine = __ldcg(hprev + base + tid);
        }

        // ---- load full h_{t-1} into registers (64 floats/lane) ----
        float hreg[64];
        const float4* h4 = (const float4*)hprev;
        #pragma unroll
        for (int j = 0; j < 8; j++) {
            float4 a = __ldcg(h4 + ((j * 32 + lane) * 2 + 0));
            float4 b = __ldcg(h4 + ((j * 32 + lane) * 2 + 1));
            hreg[j * 8 + 0] = a.x; hreg[j * 8 + 1] = a.y;
            hreg[j * 8 + 2] = a.z; hreg[j * 8 + 3] = a.w;
            hreg[j * 8 + 4] = b.x; hreg[j * 8 + 5] = b.y;
            hreg[j * 8 + 6] = b.z; hreg[j * 8 + 7] = b.w;
        }

        // ---- 6 dot products per warp (weights from SMEM, h from regs) ----
        #pragma unroll
        for (int r = 0; r < 6; r++) {
            const uint4* wp = (const uint4*)(wc + (size_t)(r0 + r) * (H / 2));
            float s0 = 0.f, s1 = 0.f, s2 = 0.f, s3 = 0.f;
            float s4 = 0.f, s5 = 0.f, s6 = 0.f, s7 = 0.f;
            #pragma unroll
            for (int j = 0; j < 8; j++) {
                uint4 w4 = wp[j * 32 + lane];       // 8 bf16 = h elems [8j..8j+7]
                s0 = fmaf(bf_lo(w4.x), hreg[j * 8 + 0], s0);
                s1 = fmaf(bf_hi(w4.x), hreg[j * 8 + 1], s1);
                s2 = fmaf(bf_lo(w4.y), hreg[j * 8 + 2], s2);
                s3 = fmaf(bf_hi(w4.y), hreg[j * 8 + 3], s3);
                s4 = fmaf(bf_lo(w4.z), hreg[j * 8 + 4], s4);
                s5 = fmaf(bf_hi(w4.z), hreg[j * 8 + 5], s5);
                s6 = fmaf(bf_lo(w4.w), hreg[j * 8 + 6], s6);
                s7 = fmaf(bf_hi(w4.w), hreg[j * 8 + 7], s7);
            }
            float s = ((s0 + s1) + (s2 + s3)) + ((s4 + s5) + (s6 + s7));
            #pragma unroll
            for (int o = 16; o; o >>= 1) s += __shfl_xor_sync(0xffffffffu, s, o);
            if (lane == 0) red[r0 + r] = s;
        }
        __syncthreads();   // (a) red[] complete

        // ---- warp 0: gate math, publish h_t, grid barrier ----
        if (wid == 0) {
            if (lane < PER) {
                const float hr = red[lane], hz = red[PER + lane], hn = red[2 * PER + lane];
                const float reset  = fsig(gr + hr);
                const float update = fsig(gz + hz);
                const float nv = ftanh(gn + reset * (hn + bnv));
                const float hnext = (1.f - update) * nv + update * hmine;
                __stcg(out + (size_t)t * H + base + lane, hnext);
                lastv = hnext;
            }
            __syncwarp();
            if (t < SEQ - 1) {
                if (lane == 0) {
                    __threadfence();                    // release own h_t stores
                    stflag(&g_flags[bid * 32], fbase + (unsigned)(t + 1));
                }
                const unsigned tgt = fbase + (unsigned)(t + 1);
                const unsigned* p0 = &g_flags[(lane +  0) * 32];
                const unsigned* p1 = &g_flags[(lane + 32) * 32];
                const unsigned* p2 = &g_flags[(lane + 64) * 32];
                const unsigned* p3 = &g_flags[(lane + 96) * 32];
                for (;;) {
                    unsigned f0 = ldflag(p0);
                    unsigned f1 = ldflag(p1);
                    unsigned f2 = ldflag(p2);
                    unsigned f3 = ldflag(p3);
                    bool ok = (f0 >= tgt) & (f1 >= tgt) & (f2 >= tgt) & (f3 >= tgt);
                    if (__all_sync(0xffffffffu, ok)) break;
                    __nanosleep(40);
                }
                __threadfence();                        // acquire
            } else {
                // final step: still advance the flag so future launches
                // (graph replays) start from a consistent epoch base.
                if (lane == 0) {
                    __threadfence();
                    stflag(&g_flags[bid * 32], fbase + (unsigned)SEQ);
                }
            }
        }
        __syncthreads();   // (c) release all warps into step t+1
    }

    if (tid < PER) out[(size_t)SEQ * H + base + tid] = lastv;
}

// ---------------- launch -----------------------------------------------------
extern "C" void kernel_launch(void* const* d_in, const int* in_sizes, int n_in,
                              void* d_out, int out_size)
{
    const float* xs         = (const float*)d_in[0];
    const float* init_state = (const float*)d_in[1];
    const float* Wi         = (const float*)d_in[2];
    const float* Wh         = (const float*)d_in[3];
    const float* bi         = (const float*)d_in[4];
    const float* bn         = (const float*)d_in[5];
    float* out = (float*)d_out;

    dim3 ggrid(G3 / GBN, SEQ / GBM);
    igates_gemm<<<ggrid, 256>>>(xs, Wi, bi);

    const size_t smem = (size_t)NROWS * (H / 2) * sizeof(unsigned)
                      + NROWS * sizeof(float);            // ~192.2 KB
    cudaFuncSetAttribute(gru_recur, cudaFuncAttributeMaxDynamicSharedMemorySize,
                         (int)smem);
    gru_recur<<<NCTA, RTH, smem>>>(init_state, Wh, bn, out);
}

// round 10
// speedup vs baseline: 1.4073x; 1.4073x over previous
#include <cuda_runtime.h>
#include <cuda_bf16.h>
#include <cstdint>
#include <math.h>

#define SEQ 4096
#define H 2048
#define IN_DIM 2048
#define G3 6144

// ---------------- scratch ---------------------------------------------------
__device__ float g_igates[(size_t)SEQ * G3];   // ~100.7 MB
__device__ unsigned int g_bar;

__global__ void init_bar_kernel() { g_bar = 0u; }

// ---------------- Kernel 1: igates = xs @ Wi^T + bi (round-2 proven) -------
#define GBM 128
#define GBN 128
#define GBK 16

__global__ __launch_bounds__(256) void igates_gemm(
    const float* __restrict__ A,
    const float* __restrict__ B,
    const float* __restrict__ bias)
{
    __shared__ float As[GBK][GBM + 1];
    __shared__ float Bs[GBK][GBN + 1];

    const int bm = blockIdx.y * GBM;
    const int bn = blockIdx.x * GBN;
    const int tid = threadIdx.x;
    const int tx = tid & 15;
    const int ty = tid >> 4;
    const int lr = tid >> 2;
    const int lc = tid & 3;

    float acc[8][8];
    #pragma unroll
    for (int i = 0; i < 8; i++)
        #pragma unroll
        for (int j = 0; j < 8; j++) acc[i][j] = 0.f;

    for (int k0 = 0; k0 < IN_DIM; k0 += GBK) {
        #pragma unroll
        for (int s = 0; s < 2; s++) {
            const int row = lr + 64 * s;
            float4 va = *(const float4*)(A + (size_t)(bm + row) * IN_DIM + k0 + 4 * lc);
            As[4*lc+0][row] = va.x; As[4*lc+1][row] = va.y;
            As[4*lc+2][row] = va.z; As[4*lc+3][row] = va.w;
            float4 vb = *(const float4*)(B + (size_t)(bn + row) * IN_DIM + k0 + 4 * lc);
            Bs[4*lc+0][row] = vb.x; Bs[4*lc+1][row] = vb.y;
            Bs[4*lc+2][row] = vb.z; Bs[4*lc+3][row] = vb.w;
        }
        __syncthreads();

        #pragma unroll
        for (int k = 0; k < GBK; k++) {
            float a[8], b[8];
            #pragma unroll
            for (int i = 0; i < 8; i++) a[i] = As[k][ty * 8 + i];
            #pragma unroll
            for (int j = 0; j < 8; j++) b[j] = Bs[k][tx * 8 + j];
            #pragma unroll
            for (int i = 0; i < 8; i++)
                #pragma unroll
                for (int j = 0; j < 8; j++) acc[i][j] += a[i] * b[j];
        }
        __syncthreads();
    }

    #pragma unroll
    for (int i = 0; i < 8; i++) {
        const int row = bm + ty * 8 + i;
        const int col = bn + tx * 8;
        float4 o0, o1;
        o0.x = acc[i][0] + bias[col + 0];
        o0.y = acc[i][1] + bias[col + 1];
        o0.z = acc[i][2] + bias[col + 2];
        o0.w = acc[i][3] + bias[col + 3];
        o1.x = acc[i][4] + bias[col + 4];
        o1.y = acc[i][5] + bias[col + 5];
        o1.z = acc[i][6] + bias[col + 6];
        o1.w = acc[i][7] + bias[col + 7];
        float* cp = g_igates + (size_t)row * G3 + col;
        *(float4*)(cp + 0) = o0;
        *(float4*)(cp + 4) = o1;
    }
}

// ---------------- Kernel 2: persistent GRU recurrence ----------------------
// Proven atomic barrier (R2 shape) + improved compute:
//  - 48 Wh rows cached in SMEM as packed bf16 (192 KB)
//  - h staged to SMEM once per CTA, copied to registers once per warp
//  - MUFU activations, early igate prefetch
#define NCTA 128
#define PER 16
#define NROWS 48
#define RTH 256

__device__ __forceinline__ float bf_lo(unsigned w) {
    return __uint_as_float(w << 16);
}
__device__ __forceinline__ float bf_hi(unsigned w) {
    return __uint_as_float(w & 0xFFFF0000u);
}
__device__ __forceinline__ float fsig(float x) {
    return __fdividef(1.f, 1.f + __expf(-x));
}
__device__ __forceinline__ float ftanh(float x) {
    return __fdividef(2.f, 1.f + __expf(-2.f * x)) - 1.f;
}

__global__ __launch_bounds__(RTH, 1) void gru_recur(
    const float* __restrict__ init_state,
    const float* __restrict__ Wh,
    const float* __restrict__ bn,
    float* __restrict__ out)
{
    extern __shared__ float smem[];
    unsigned* wc = (unsigned*)smem;                        // NROWS * H/2 words (192KB)
    float* h_s   = (float*)(wc + (size_t)NROWS * (H/2));   // H floats (8KB)
    float* red   = h_s + H;                                // NROWS floats

    const int tid  = threadIdx.x;
    const int lane = tid & 31;
    const int wid  = tid >> 5;
    const int base = blockIdx.x * PER;
    const int r0   = wid * 6;            // this warp's 6 rows

    // prologue: convert+cache 48 Wh rows as packed bf16 (lo=elem 2v, hi=2v+1)
    for (int r = 0; r < NROWS; r++) {
        const int gate = r / PER, i = r % PER;
        const float2* src = (const float2*)(Wh + (size_t)(gate * H + base + i) * H);
        unsigned* dst = wc + (size_t)r * (H / 2);
        for (int v = tid; v < H / 2; v += RTH) {
            float2 w = src[v];
            __nv_bfloat162 b2 = __floats2bfloat162_rn(w.x, w.y);
            dst[v] = *(unsigned*)&b2;
        }
    }
    __syncthreads();   // order prologue wc writes vs first-step reads

    float bnv = 0.f, lastv = 0.f;
    if (tid < PER) bnv = bn[base + tid];

    for (int t = 0; t < SEQ; t++) {
        const float* hprev = (t == 0) ? init_state : (out + (size_t)(t - 1) * H);

        // early reads: igates (DRAM); consumed in the epilogue
        float gr = 0.f, gz = 0.f, gn = 0.f;
        if (tid < PER) {
            const float* ig = g_igates + (size_t)t * G3;
            gr = ig[base + tid];
            gz = ig[H + base + tid];
            gn = ig[2 * H + base + tid];
        }

        // ---- stage h_{t-1} into SMEM once per CTA (one 8KB L2 read) ----
        {
            const float4* h4 = (const float4*)hprev;
            float4* d4 = (float4*)h_s;
            d4[tid]       = __ldcg(h4 + tid);
            d4[tid + RTH] = __ldcg(h4 + tid + RTH);
        }
        __syncthreads();

        // ---- copy h from SMEM into registers once per warp ----
        float hreg[64];
        {
            const float4* hs4 = (const float4*)h_s;
            #pragma unroll
            for (int j = 0; j < 8; j++) {
                float4 a = hs4[(j * 32 + lane) * 2 + 0];
                float4 b = hs4[(j * 32 + lane) * 2 + 1];
                hreg[j * 8 + 0] = a.x; hreg[j * 8 + 1] = a.y;
                hreg[j * 8 + 2] = a.z; hreg[j * 8 + 3] = a.w;
                hreg[j * 8 + 4] = b.x; hreg[j * 8 + 5] = b.y;
                hreg[j * 8 + 6] = b.z; hreg[j * 8 + 7] = b.w;
            }
        }

        // ---- 6 dot products per warp (weights from SMEM, h from regs) ----
        #pragma unroll
        for (int r = 0; r < 6; r++) {
            const uint4* wp = (const uint4*)(wc + (size_t)(r0 + r) * (H / 2));
            float s0 = 0.f, s1 = 0.f, s2 = 0.f, s3 = 0.f;
            float s4 = 0.f, s5 = 0.f, s6 = 0.f, s7 = 0.f;
            #pragma unroll
            for (int j = 0; j < 8; j++) {
                uint4 w4 = wp[j * 32 + lane];       // 8 bf16 = h elems [8j..8j+7]
                s0 = fmaf(bf_lo(w4.x), hreg[j * 8 + 0], s0);
                s1 = fmaf(bf_hi(w4.x), hreg[j * 8 + 1], s1);
                s2 = fmaf(bf_lo(w4.y), hreg[j * 8 + 2], s2);
                s3 = fmaf(bf_hi(w4.y), hreg[j * 8 + 3], s3);
                s4 = fmaf(bf_lo(w4.z), hreg[j * 8 + 4], s4);
                s5 = fmaf(bf_hi(w4.z), hreg[j * 8 + 5], s5);
                s6 = fmaf(bf_lo(w4.w), hreg[j * 8 + 6], s6);
                s7 = fmaf(bf_hi(w4.w), hreg[j * 8 + 7], s7);
            }
            float s = ((s0 + s1) + (s2 + s3)) + ((s4 + s5) + (s6 + s7));
            #pragma unroll
            for (int o = 16; o; o >>= 1) s += __shfl_xor_sync(0xffffffffu, s, o);
            if (lane == 0) red[r0 + r] = s;
        }
        __syncthreads();   // red[] complete

        // ---- gate math + write h_t (threads 0..15, inside warp 0) ----
        if (tid < PER) {
            const float hr = red[tid], hz = red[PER + tid], hn = red[2 * PER + tid];
            const float reset  = fsig(gr + hr);
            const float update = fsig(gz + hz);
            const float nv = ftanh(gn + reset * (hn + bnv));
            const float hnext = (1.f - update) * nv + update * h_s[base + tid];
            __stcg(out + (size_t)t * H + base + tid, hnext);
            lastv = hnext;
        }
        __threadfence();   // release h_t stores device-wide
        __syncthreads();

        // ---- grid barrier (PROVEN: atomic + volatile spin, thread 0) ----
        if (tid == 0) {
            atomicAdd(&g_bar, 1u);
            const unsigned target = (unsigned)(t + 1) * NCTA;
            while (*((volatile unsigned int*)&g_bar) < target) { }
            __threadfence();   // acquire
        }
        __syncthreads();
    }

    if (tid < PER) out[(size_t)SEQ * H + base + tid] = lastv;
}

// ---------------- launch -----------------------------------------------------
extern "C" void kernel_launch(void* const* d_in, const int* in_sizes, int n_in,
                              void* d_out, int out_size)
{
    const float* xs         = (const float*)d_in[0];
    const float* init_state = (const float*)d_in[1];
    const float* Wi         = (const float*)d_in[2];
    const float* Wh         = (const float*)d_in[3];
    const float* bi         = (const float*)d_in[4];
    const float* bn         = (const float*)d_in[5];
    float* out = (float*)d_out;

    init_bar_kernel<<<1, 1>>>();

    dim3 ggrid(G3 / GBN, SEQ / GBM);
    igates_gemm<<<ggrid, 256>>>(xs, Wi, bi);

    const size_t smem = (size_t)NROWS * (H / 2) * sizeof(unsigned)   // weights
                      + (size_t)H * sizeof(float)                     // h stage
                      + NROWS * sizeof(float);                        // red
    cudaFuncSetAttribute(gru_recur, cudaFuncAttributeMaxDynamicSharedMemorySize,
                         (int)smem);
    gru_recur<<<NCTA, RTH, smem>>>(init_state, Wh, bn, out);
}

// round 11
// speedup vs baseline: 1.4610x; 1.0382x over previous
#include <cuda_runtime.h>
#include <cuda_bf16.h>
#include <cstdint>
#include <math.h>

#define SEQ 4096
#define H 2048
#define IN_DIM 2048
#define G3 6144

typedef unsigned long long ull;

// ---------------- scratch ---------------------------------------------------
__device__ float g_igates[(size_t)SEQ * G3];   // ~100.7 MB
__device__ unsigned int g_bar;

__global__ void init_bar_kernel() { g_bar = 0u; }

// ---------------- packed fp32x2 helpers (GEMM only) -------------------------
__device__ __forceinline__ ull pack_f32x2(float lo, float hi) {
    ull u;
    asm("mov.b64 %0, {%1, %2};" : "=l"(u)
        : "r"(__float_as_uint(lo)), "r"(__float_as_uint(hi)));
    return u;
}
__device__ __forceinline__ ull dup_f32x2(float a) {
    ull u;
    asm("mov.b64 %0, {%1, %1};" : "=l"(u) : "r"(__float_as_uint(a)));
    return u;
}
__device__ __forceinline__ void ffma2(ull& acc, ull a, ull b) {
    asm("fma.rn.f32x2 %0, %1, %2, %0;" : "+l"(acc) : "l"(a), "l"(b));
}
__device__ __forceinline__ float2 unpack_f32x2(ull u) {
    unsigned lo, hi;
    asm("mov.b64 {%0, %1}, %2;" : "=r"(lo), "=r"(hi) : "l"(u));
    float2 f; f.x = __uint_as_float(lo); f.y = __uint_as_float(hi);
    return f;
}

// ---------------- Kernel 1: igates = xs @ Wi^T + bi (FFMA2 inner) ----------
#define GBM 128
#define GBN 128
#define GBK 16

__global__ __launch_bounds__(256) void igates_gemm(
    const float* __restrict__ A,
    const float* __restrict__ B,
    const float* __restrict__ bias)
{
    __shared__ __align__(16) float As[GBK][GBM + 4];
    __shared__ __align__(16) float Bs[GBK][GBN + 4];

    const int bm = blockIdx.y * GBM;
    const int bn = blockIdx.x * GBN;
    const int tid = threadIdx.x;
    const int tx = tid & 15;
    const int ty = tid >> 4;
    const int lr = tid >> 2;
    const int lc = tid & 3;

    ull acc2[8][4];
    #pragma unroll
    for (int i = 0; i < 8; i++)
        #pragma unroll
        for (int p = 0; p < 4; p++) acc2[i][p] = 0ull;

    for (int k0 = 0; k0 < IN_DIM; k0 += GBK) {
        #pragma unroll
        for (int s = 0; s < 2; s++) {
            const int row = lr + 64 * s;
            float4 va = *(const float4*)(A + (size_t)(bm + row) * IN_DIM + k0 + 4 * lc);
            As[4*lc+0][row] = va.x; As[4*lc+1][row] = va.y;
            As[4*lc+2][row] = va.z; As[4*lc+3][row] = va.w;
            float4 vb = *(const float4*)(B + (size_t)(bn + row) * IN_DIM + k0 + 4 * lc);
            Bs[4*lc+0][row] = vb.x; Bs[4*lc+1][row] = vb.y;
            Bs[4*lc+2][row] = vb.z; Bs[4*lc+3][row] = vb.w;
        }
        __syncthreads();

        #pragma unroll
        for (int k = 0; k < GBK; k++) {
            float4 a0 = *(const float4*)&As[k][ty * 8];
            float4 a1 = *(const float4*)&As[k][ty * 8 + 4];
            float4 b0 = *(const float4*)&Bs[k][tx * 8];
            float4 b1 = *(const float4*)&Bs[k][tx * 8 + 4];
            ull bp[4];
            bp[0] = pack_f32x2(b0.x, b0.y);
            bp[1] = pack_f32x2(b0.z, b0.w);
            bp[2] = pack_f32x2(b1.x, b1.y);
            bp[3] = pack_f32x2(b1.z, b1.w);
            float av[8] = {a0.x, a0.y, a0.z, a0.w, a1.x, a1.y, a1.z, a1.w};
            #pragma unroll
            for (int i = 0; i < 8; i++) {
                ull ad = dup_f32x2(av[i]);
                #pragma unroll
                for (int p = 0; p < 4; p++) ffma2(acc2[i][p], ad, bp[p]);
            }
        }
        __syncthreads();
    }

    #pragma unroll
    for (int i = 0; i < 8; i++) {
        const int row = bm + ty * 8 + i;
        const int col = bn + tx * 8;
        float2 c0 = unpack_f32x2(acc2[i][0]);
        float2 c1 = unpack_f32x2(acc2[i][1]);
        float2 c2 = unpack_f32x2(acc2[i][2]);
        float2 c3 = unpack_f32x2(acc2[i][3]);
        float4 o0, o1;
        o0.x = c0.x + bias[col + 0]; o0.y = c0.y + bias[col + 1];
        o0.z = c1.x + bias[col + 2]; o0.w = c1.y + bias[col + 3];
        o1.x = c2.x + bias[col + 4]; o1.y = c2.y + bias[col + 5];
        o1.z = c3.x + bias[col + 6]; o1.w = c3.y + bias[col + 7];
        float* cp = g_igates + (size_t)row * G3 + col;
        *(float4*)(cp + 0) = o0;
        *(float4*)(cp + 4) = o1;
    }
}

// ---------------- Kernel 2: persistent GRU recurrence ----------------------
// R10 compute (proven) + slimmed epilogue: single-thread cumulative fences,
// one syncthreads removed. Barrier mechanism unchanged (atomic + volatile).
#define NCTA 128
#define PER 16
#define NROWS 48
#define RTH 256

__device__ __forceinline__ float bf_lo(unsigned w) {
    return __uint_as_float(w << 16);
}
__device__ __forceinline__ float bf_hi(unsigned w) {
    return __uint_as_float(w & 0xFFFF0000u);
}
__device__ __forceinline__ float fsig(float x) {
    return __fdividef(1.f, 1.f + __expf(-x));
}
__device__ __forceinline__ float ftanh(float x) {
    return __fdividef(2.f, 1.f + __expf(-2.f * x)) - 1.f;
}

__global__ __launch_bounds__(RTH, 1) void gru_recur(
    const float* __restrict__ init_state,
    const float* __restrict__ Wh,
    const float* __restrict__ bn,
    float* __restrict__ out)
{
    extern __shared__ float smem[];
    unsigned* wc = (unsigned*)smem;                        // NROWS * H/2 words (192KB)
    float* h_s   = (float*)(wc + (size_t)NROWS * (H/2));   // H floats (8KB)
    float* red   = h_s + H;                                // NROWS floats

    const int tid  = threadIdx.x;
    const int lane = tid & 31;
    const int wid  = tid >> 5;
    const int base = blockIdx.x * PER;
    const int r0   = wid * 6;            // this warp's 6 rows

    // prologue: convert+cache 48 Wh rows as packed bf16 (lo=elem 2v, hi=2v+1)
    for (int r = 0; r < NROWS; r++) {
        const int gate = r / PER, i = r % PER;
        const float2* src = (const float2*)(Wh + (size_t)(gate * H + base + i) * H);
        unsigned* dst = wc + (size_t)r * (H / 2);
        for (int v = tid; v < H / 2; v += RTH) {
            float2 w = src[v];
            __nv_bfloat162 b2 = __floats2bfloat162_rn(w.x, w.y);
            dst[v] = *(unsigned*)&b2;
        }
    }
    __syncthreads();   // order prologue wc writes vs first-step reads

    float bnv = 0.f, lastv = 0.f;
    if (tid < PER) bnv = bn[base + tid];

    for (int t = 0; t < SEQ; t++) {
        const float* hprev = (t == 0) ? init_state : (out + (size_t)(t - 1) * H);

        // early reads: igates (DRAM); consumed in the epilogue
        float gr = 0.f, gz = 0.f, gn = 0.f;
        if (tid < PER) {
            const float* ig = g_igates + (size_t)t * G3;
            gr = ig[base + tid];
            gz = ig[H + base + tid];
            gn = ig[2 * H + base + tid];
        }

        // ---- stage h_{t-1} into SMEM once per CTA (one 8KB L2 read) ----
        {
            const float4* h4 = (const float4*)hprev;
            float4* d4 = (float4*)h_s;
            d4[tid]       = __ldcg(h4 + tid);
            d4[tid + RTH] = __ldcg(h4 + tid + RTH);
        }
        __syncthreads();

        // ---- copy h from SMEM into registers once per warp ----
        float hreg[64];
        {
            const float4* hs4 = (const float4*)h_s;
            #pragma unroll
            for (int j = 0; j < 8; j++) {
                float4 a = hs4[(j * 32 + lane) * 2 + 0];
                float4 b = hs4[(j * 32 + lane) * 2 + 1];
                hreg[j * 8 + 0] = a.x; hreg[j * 8 + 1] = a.y;
                hreg[j * 8 + 2] = a.z; hreg[j * 8 + 3] = a.w;
                hreg[j * 8 + 4] = b.x; hreg[j * 8 + 5] = b.y;
                hreg[j * 8 + 6] = b.z; hreg[j * 8 + 7] = b.w;
            }
        }

        // ---- 6 dot products per warp (weights from SMEM, h from regs) ----
        #pragma unroll
        for (int r = 0; r < 6; r++) {
            const uint4* wp = (const uint4*)(wc + (size_t)(r0 + r) * (H / 2));
            float s0 = 0.f, s1 = 0.f, s2 = 0.f, s3 = 0.f;
            float s4 = 0.f, s5 = 0.f, s6 = 0.f, s7 = 0.f;
            #pragma unroll
            for (int j = 0; j < 8; j++) {
                uint4 w4 = wp[j * 32 + lane];       // 8 bf16 = h elems [8j..8j+7]
                s0 = fmaf(bf_lo(w4.x), hreg[j * 8 + 0], s0);
                s1 = fmaf(bf_hi(w4.x), hreg[j * 8 + 1], s1);
                s2 = fmaf(bf_lo(w4.y), hreg[j * 8 + 2], s2);
                s3 = fmaf(bf_hi(w4.y), hreg[j * 8 + 3], s3);
                s4 = fmaf(bf_lo(w4.z), hreg[j * 8 + 4], s4);
                s5 = fmaf(bf_hi(w4.z), hreg[j * 8 + 5], s5);
                s6 = fmaf(bf_lo(w4.w), hreg[j * 8 + 6], s6);
                s7 = fmaf(bf_hi(w4.w), hreg[j * 8 + 7], s7);
            }
            float s = ((s0 + s1) + (s2 + s3)) + ((s4 + s5) + (s6 + s7));
            #pragma unroll
            for (int o = 16; o; o >>= 1) s += __shfl_xor_sync(0xffffffffu, s, o);
            if (lane == 0) red[r0 + r] = s;
        }
        __syncthreads();   // red[] complete

        // ---- warp 0: gates + publish + barrier (cumulative-fence slim) ----
        if (wid == 0) {
            if (lane < PER) {
                const float hr = red[lane], hz = red[PER + lane], hn = red[2 * PER + lane];
                const float reset  = fsig(gr + hr);
                const float update = fsig(gz + hz);
                const float nv = ftanh(gn + reset * (hn + bnv));
                const float hnext = (1.f - update) * nv + update * h_s[base + lane];
                __stcg(out + (size_t)t * H + base + lane, hnext);
                lastv = hnext;
            }
            __syncwarp();                       // warp-scope ordering of lanes' stores
            if (lane == 0) {
                __threadfence();                // cumulative release (covers lanes 0-15)
                atomicAdd(&g_bar, 1u);
                const unsigned target = (unsigned)(t + 1) * NCTA;
                while (*((volatile unsigned int*)&g_bar) < target) { }
                __threadfence();                // cumulative acquire
            }
            __syncwarp();
        }
        __syncthreads();   // propagate acquire CTA-wide; release into step t+1
    }

    if (tid < PER) out[(size_t)SEQ * H + base + tid] = lastv;
}

// ---------------- launch -----------------------------------------------------
extern "C" void kernel_launch(void* const* d_in, const int* in_sizes, int n_in,
                              void* d_out, int out_size)
{
    const float* xs         = (const float*)d_in[0];
    const float* init_state = (const float*)d_in[1];
    const float* Wi         = (const float*)d_in[2];
    const float* Wh         = (const float*)d_in[3];
    const float* bi         = (const float*)d_in[4];
    const float* bn         = (const float*)d_in[5];
    float* out = (float*)d_out;

    init_bar_kernel<<<1, 1>>>();

    dim3 ggrid(G3 / GBN, SEQ / GBM);
    igates_gemm<<<ggrid, 256>>>(xs, Wi, bi);

    const size_t smem = (size_t)NROWS * (H / 2) * sizeof(unsigned)   // weights
                      + (size_t)H * sizeof(float)                     // h stage
                      + NROWS * sizeof(float);                        // red
    cudaFuncSetAttribute(gru_recur, cudaFuncAttributeMaxDynamicSharedMemorySize,
                         (int)smem);
    gru_recur<<<NCTA, RTH, smem>>>(init_state, Wh, bn, out);
}

// round 13
// speedup vs baseline: 1.5496x; 1.0606x over previous
#include <cuda_runtime.h>
#include <cuda_bf16.h>
#include <cstdint>
#include <math.h>

#define SEQ 4096
#define H 2048
#define IN_DIM 2048
#define G3 6144

// ---------------- scratch ---------------------------------------------------
__device__ float g_igates[(size_t)SEQ * G3];   // ~100.7 MB
__device__ unsigned int g_bar;

__global__ void init_bar_kernel() { g_bar = 0u; }

// ---------------- tf32 mma helpers ------------------------------------------
__device__ __forceinline__ unsigned f2tf32(float f) {
    unsigned u;
    asm("cvt.rna.tf32.f32 %0, %1;" : "=r"(u) : "f"(f));
    return u;
}
__device__ __forceinline__ void mma_tf32(float* c, const unsigned* a,
                                         const unsigned* b) {
    asm volatile(
        "mma.sync.aligned.m16n8k8.row.col.f32.tf32.tf32.f32 "
        "{%0,%1,%2,%3}, {%4,%5,%6,%7}, {%8,%9}, {%0,%1,%2,%3};\n"
        : "+f"(c[0]), "+f"(c[1]), "+f"(c[2]), "+f"(c[3])
        : "r"(a[0]), "r"(a[1]), "r"(a[2]), "r"(a[3]), "r"(b[0]), "r"(b[1]));
}

// ---------------- Kernel 1: igates = xs @ Wi^T + bi (tf32 tensor cores) ----
// CTA tile 128(M)x128(N), 8 warps each 32x64. K-chunk 16.
#define TM 128
#define TN 128
#define TK 16

__global__ __launch_bounds__(256) void igates_gemm(
    const float* __restrict__ A,      // xs [4096,2048] row-major
    const float* __restrict__ B,      // Wi [6144,2048] row-major
    const float* __restrict__ bias)
{
    __shared__ unsigned As[TM][TK + 1];
    __shared__ unsigned Bs[TN][TK + 1];

    const int tid  = threadIdx.x;
    const int lane = tid & 31;
    const int wid  = tid >> 5;
    const int mw   = wid & 3;          // warp M index (0..3) -> m offset mw*32
    const int nw   = wid >> 2;         // warp N index (0..1) -> n offset nw*64
    const int bm   = blockIdx.y * TM;
    const int bn   = blockIdx.x * TN;
    const int grp  = lane >> 2;        // 0..7
    const int tig  = lane & 3;         // 0..3

    float c[16][4];                    // [mi*8+ni][reg]
    #pragma unroll
    for (int i = 0; i < 16; i++)
        #pragma unroll
        for (int j = 0; j < 4; j++) c[i][j] = 0.f;

    for (int k0 = 0; k0 < IN_DIM; k0 += TK) {
        // load 128x16 of A and B, convert to tf32, store to smem
        #pragma unroll
        for (int i = 0; i < 2; i++) {
            const int id  = tid + i * 256;     // 0..511
            const int row = id >> 2;
            const int c4  = (id & 3) * 4;
            float4 va = *(const float4*)(A + (size_t)(bm + row) * IN_DIM + k0 + c4);
            As[row][c4 + 0] = f2tf32(va.x);
            As[row][c4 + 1] = f2tf32(va.y);
            As[row][c4 + 2] = f2tf32(va.z);
            As[row][c4 + 3] = f2tf32(va.w);
            float4 vb = *(const float4*)(B + (size_t)(bn + row) * IN_DIM + k0 + c4);
            Bs[row][c4 + 0] = f2tf32(vb.x);
            Bs[row][c4 + 1] = f2tf32(vb.y);
            Bs[row][c4 + 2] = f2tf32(vb.z);
            Bs[row][c4 + 3] = f2tf32(vb.w);
        }
        __syncthreads();

        #pragma unroll
        for (int kk = 0; kk < TK; kk += 8) {
            // A fragments: 2 x m16k8
            unsigned af[2][4];
            #pragma unroll
            for (int mi = 0; mi < 2; mi++) {
                const int r = mw * 32 + mi * 16 + grp;
                af[mi][0] = As[r][kk + tig];
                af[mi][1] = As[r + 8][kk + tig];
                af[mi][2] = As[r][kk + tig + 4];
                af[mi][3] = As[r + 8][kk + tig + 4];
            }
            // B fragments + mma: 8 x k8n8
            #pragma unroll
            for (int ni = 0; ni < 8; ni++) {
                const int n = nw * 64 + ni * 8 + grp;
                unsigned bf[2];
                bf[0] = Bs[n][kk + tig];
                bf[1] = Bs[n][kk + tig + 4];
                mma_tf32(c[ni], af[0], bf);
                mma_tf32(c[8 + ni], af[1], bf);
            }
        }
        __syncthreads();
    }

    // epilogue: add bias, write to g_igates
    #pragma unroll
    for (int mi = 0; mi < 2; mi++) {
        #pragma unroll
        for (int ni = 0; ni < 8; ni++) {
            const float* cf = c[mi * 8 + ni];
            const int row = bm + mw * 32 + mi * 16 + grp;
            const int col = bn + nw * 64 + ni * 8 + 2 * tig;
            const float b0 = bias[col], b1 = bias[col + 1];
            float2 v01; v01.x = cf[0] + b0; v01.y = cf[1] + b1;
            float2 v23; v23.x = cf[2] + b0; v23.y = cf[3] + b1;
            *(float2*)(g_igates + (size_t)row * G3 + col) = v01;
            *(float2*)(g_igates + (size_t)(row + 8) * G3 + col) = v23;
        }
    }
}

// ---------------- Kernel 2: persistent GRU recurrence (R11 proven, exact) --
#define NCTA 128
#define PER 16
#define NROWS 48
#define RTH 256

__device__ __forceinline__ float bf_lo(unsigned w) {
    return __uint_as_float(w << 16);
}
__device__ __forceinline__ float bf_hi(unsigned w) {
    return __uint_as_float(w & 0xFFFF0000u);
}
__device__ __forceinline__ float fsig(float x) {
    return __fdividef(1.f, 1.f + __expf(-x));
}
__device__ __forceinline__ float ftanh(float x) {
    return __fdividef(2.f, 1.f + __expf(-2.f * x)) - 1.f;
}

__global__ __launch_bounds__(RTH, 1) void gru_recur(
    const float* __restrict__ init_state,
    const float* __restrict__ Wh,
    const float* __restrict__ bn,
    float* __restrict__ out)
{
    extern __shared__ float smem[];
    unsigned* wc = (unsigned*)smem;                        // NROWS * H/2 words (192KB)
    float* h_s   = (float*)(wc + (size_t)NROWS * (H/2));   // H floats (8KB)
    float* red   = h_s + H;                                // NROWS floats

    const int tid  = threadIdx.x;
    const int lane = tid & 31;
    const int wid  = tid >> 5;
    const int base = blockIdx.x * PER;
    const int r0   = wid * 6;            // this warp's 6 rows

    // prologue: convert+cache 48 Wh rows as packed bf16 (lo=elem 2v, hi=2v+1)
    for (int r = 0; r < NROWS; r++) {
        const int gate = r / PER, i = r % PER;
        const float2* src = (const float2*)(Wh + (size_t)(gate * H + base + i) * H);
        unsigned* dst = wc + (size_t)r * (H / 2);
        for (int v = tid; v < H / 2; v += RTH) {
            float2 w = src[v];
            __nv_bfloat162 b2 = __floats2bfloat162_rn(w.x, w.y);
            dst[v] = *(unsigned*)&b2;
        }
    }
    __syncthreads();   // order prologue wc writes vs first-step reads

    float bnv = 0.f, lastv = 0.f;
    if (tid < PER) bnv = bn[base + tid];

    for (int t = 0; t < SEQ; t++) {
        const float* hprev = (t == 0) ? init_state : (out + (size_t)(t - 1) * H);

        // early reads: igates (DRAM); consumed in the epilogue
        float gr = 0.f, gz = 0.f, gn = 0.f;
        if (tid < PER) {
            const float* ig = g_igates + (size_t)t * G3;
            gr = ig[base + tid];
            gz = ig[H + base + tid];
            gn = ig[2 * H + base + tid];
        }

        // ---- stage h_{t-1} into SMEM once per CTA (one 8KB L2 read) ----
        {
            const float4* h4 = (const float4*)hprev;
            float4* d4 = (float4*)h_s;
            d4[tid]       = __ldcg(h4 + tid);
            d4[tid + RTH] = __ldcg(h4 + tid + RTH);
        }
        __syncthreads();

        // ---- copy h from SMEM into registers once per warp ----
        float hreg[64];
        {
            const float4* hs4 = (const float4*)h_s;
            #pragma unroll
            for (int j = 0; j < 8; j++) {
                float4 a = hs4[(j * 32 + lane) * 2 + 0];
                float4 b = hs4[(j * 32 + lane) * 2 + 1];
                hreg[j * 8 + 0] = a.x; hreg[j * 8 + 1] = a.y;
                hreg[j * 8 + 2] = a.z; hreg[j * 8 + 3] = a.w;
                hreg[j * 8 + 4] = b.x; hreg[j * 8 + 5] = b.y;
                hreg[j * 8 + 6] = b.z; hreg[j * 8 + 7] = b.w;
            }
        }

        // ---- 6 dot products per warp (weights from SMEM, h from regs) ----
        #pragma unroll
        for (int r = 0; r < 6; r++) {
            const uint4* wp = (const uint4*)(wc + (size_t)(r0 + r) * (H / 2));
            float s0 = 0.f, s1 = 0.f, s2 = 0.f, s3 = 0.f;
            float s4 = 0.f, s5 = 0.f, s6 = 0.f, s7 = 0.f;
            #pragma unroll
            for (int j = 0; j < 8; j++) {
                uint4 w4 = wp[j * 32 + lane];       // 8 bf16 = h elems [8j..8j+7]
                s0 = fmaf(bf_lo(w4.x), hreg[j * 8 + 0], s0);
                s1 = fmaf(bf_hi(w4.x), hreg[j * 8 + 1], s1);
                s2 = fmaf(bf_lo(w4.y), hreg[j * 8 + 2], s2);
                s3 = fmaf(bf_hi(w4.y), hreg[j * 8 + 3], s3);
                s4 = fmaf(bf_lo(w4.z), hreg[j * 8 + 4], s4);
                s5 = fmaf(bf_hi(w4.z), hreg[j * 8 + 5], s5);
                s6 = fmaf(bf_lo(w4.w), hreg[j * 8 + 6], s6);
                s7 = fmaf(bf_hi(w4.w), hreg[j * 8 + 7], s7);
            }
            float s = ((s0 + s1) + (s2 + s3)) + ((s4 + s5) + (s6 + s7));
            #pragma unroll
            for (int o = 16; o; o >>= 1) s += __shfl_xor_sync(0xffffffffu, s, o);
            if (lane == 0) red[r0 + r] = s;
        }
        __syncthreads();   // red[] complete

        // ---- warp 0: gates + publish + barrier (PROVEN single-line spin) ----
        if (wid == 0) {
            if (lane < PER) {
                const float hr = red[lane], hz = red[PER + lane], hn = red[2 * PER + lane];
                const float reset  = fsig(gr + hr);
                const float update = fsig(gz + hz);
                const float nv = ftanh(gn + reset * (hn + bnv));
                const float hnext = (1.f - update) * nv + update * h_s[base + lane];
                __stcg(out + (size_t)t * H + base + lane, hnext);
                lastv = hnext;
            }
            __syncwarp();                       // warp-scope ordering of lanes' stores
            if (lane == 0) {
                __threadfence();                // cumulative release (covers lanes 0-15)
                atomicAdd(&g_bar, 1u);
                const unsigned target = (unsigned)(t + 1) * NCTA;
                while (*((volatile unsigned int*)&g_bar) < target) { }
                __threadfence();                // cumulative acquire
            }
            __syncwarp();
        }
        __syncthreads();   // propagate acquire CTA-wide; release into step t+1
    }

    if (tid < PER) out[(size_t)SEQ * H + base + tid] = lastv;
}

// ---------------- launch -----------------------------------------------------
extern "C" void kernel_launch(void* const* d_in, const int* in_sizes, int n_in,
                              void* d_out, int out_size)
{
    const float* xs         = (const float*)d_in[0];
    const float* init_state = (const float*)d_in[1];
    const float* Wi         = (const float*)d_in[2];
    const float* Wh         = (const float*)d_in[3];
    const float* bi         = (const float*)d_in[4];
    const float* bn         = (const float*)d_in[5];
    float* out = (float*)d_out;

    init_bar_kernel<<<1, 1>>>();

    dim3 ggrid(G3 / TN, SEQ / TM);     // (48, 32)
    igates_gemm<<<ggrid, 256>>>(xs, Wi, bi);

    const size_t smem = (size_t)NROWS * (H / 2) * sizeof(unsigned)   // weights
                      + (size_t)H * sizeof(float)                     // h stage
                      + NROWS * sizeof(float);                        // red
    cudaFuncSetAttribute(gru_recur, cudaFuncAttributeMaxDynamicSharedMemorySize,
                         (int)smem);
    gru_recur<<<NCTA, RTH, smem>>>(init_state, Wh, bn, out);
}